// round 14
// baseline (speedup 1.0000x reference)
#include <cuda_runtime.h>
#include <cstdint>

#define IN_H   1024
#define IN_W   1024
#define OUT_H  256
#define OUT_W  256
#define NTAP   16

#define VCHUNK 4                 // output rows per strip
#define VROWS  (4*VCHUNK + 12)   // 28 input rows per strip
#define G      2                 // input rows per cp.async group (8 KB)
#define NG     (VROWS / G)       // 14 groups per strip
#define STRIPS 2
#define NSTRIP_IMG (OUT_H / VCHUNK)          // 64 strips per image
#define XBLKS  (NSTRIP_IMG / STRIPS)         // 32 block columns
#define TOTQ   (STRIPS * NG)                 // 28

// static smem: ring[3][G][IN_W] (24 KB) + v4[VCHUNK][IN_W] (16 KB) = 40 KB

__device__ __forceinline__ void cp_async16(uint32_t dst_smem, const float* src) {
    asm volatile("cp.async.cg.shared.global [%0], [%1], 16;\n"
                 :: "r"(dst_smem), "l"(src) : "memory");
}
__device__ __forceinline__ void cp_commit() {
    asm volatile("cp.async.commit_group;\n" ::: "memory");
}
template <int N>
__device__ __forceinline__ void cp_wait() {
    asm volatile("cp.async.wait_group %0;\n" :: "n"(N) : "memory");
}

__global__ __launch_bounds__(256, 5)
void bicubic_fused(const float* __restrict__ in, float* __restrict__ out)
{
    constexpr float W[NTAP] = {
        -0.001708984375f, -0.010986328125f, -0.018310546875f, -0.011962890625f,
         0.022705078125f,  0.097412109375f,  0.181884765625f,  0.240966796875f,
         0.240966796875f,  0.181884765625f,  0.097412109375f,  0.022705078125f,
        -0.011962890625f, -0.018310546875f, -0.010986328125f, -0.001708984375f };

    __shared__ __align__(16) float ring[3][G][IN_W];   // 24 KB
    __shared__ __align__(16) float v4[VCHUNK][IN_W];   // 16 KB

    const int tid = threadIdx.x;                 // owns float4 column tid
    const int img = blockIdx.y;
    const float* __restrict__ inp = in + (size_t)img * (IN_H * IN_W);

    // issue group q (global counter across both strips) into ring[q%3]
    auto issue = [&](int q) {
        const int s     = q / NG;
        const int g     = q % NG;
        const int strip = blockIdx.x + XBLKS * s;        // 0..63
        const int R0    = 4 * strip * VCHUNK - 6;
#pragma unroll
        for (int r = 0; r < G; ++r) {
            const int gr = min(max(R0 + G * g + r, 0), IN_H - 1);
            const uint32_t dst = (uint32_t)__cvta_generic_to_shared(
                &ring[q % 3][r][4 * tid]);
            cp_async16(dst, inp + (size_t)gr * IN_W + 4 * tid);
        }
        cp_commit();
    };

    issue(0);
    issue(1);

#pragma unroll
    for (int it = 0; it < STRIPS; ++it) {
        const int strip = blockIdx.x + XBLKS * it;
        const int o0    = strip * VCHUNK;
        float* __restrict__ outp = out + ((size_t)img * OUT_H + o0) * OUT_W;

        float4 acc[VCHUNK];
#pragma unroll
        for (int j = 0; j < VCHUNK; ++j) acc[j] = make_float4(0.f, 0.f, 0.f, 0.f);

        // ---- barrier-free V mainloop; cp stream continuous across strips ----
#pragma unroll
        for (int g = 0; g < NG; ++g) {
            const int q = it * NG + g;
            if (q + 2 < TOTQ) { issue(q + 2); cp_wait<2>(); }
            else if (q + 1 < TOTQ) cp_wait<1>();
            else cp_wait<0>();

            const float4* __restrict__ buf = (const float4*)ring[q % 3];
#pragma unroll
            for (int r = 0; r < G; ++r) {
                const int i = G * g + r;
                const float4 x = buf[r * (IN_W / 4) + tid];
#pragma unroll
                for (int j = 0; j < VCHUNK; ++j) {
                    const int k = i - 4 * j;               // compile-time pruned
                    if (k >= 0 && k < NTAP) {
                        acc[j].x = fmaf(W[k], x.x, acc[j].x);
                        acc[j].y = fmaf(W[k], x.y, acc[j].y);
                        acc[j].z = fmaf(W[k], x.z, acc[j].z);
                        acc[j].w = fmaf(W[k], x.w, acc[j].w);
                    }
                }
            }
        }

        // ---- H phase: publish 4 rows, 16-tap with register center ----
#pragma unroll
        for (int j = 0; j < VCHUNK; ++j)
            ((float4*)v4[j])[tid] = acc[j];
        __syncthreads();

        const int oc = tid;
#pragma unroll
        for (int j = 0; j < VCHUNK; ++j) {
            const float* __restrict__ srow = v4[j];
            float r;
            if (oc >= 2 && oc <= 253) {
                const float4* __restrict__ sv = (const float4*)srow + oc;
                const float4 a = sv[-2], b = sv[-1], d = sv[1], e = sv[2];
                const float4 c = acc[j];         // own dump, still in registers
                r = W[0] * a.z;                  // tap 0 = v[4oc-6]
                r = fmaf(W[1],  a.w, r);  r = fmaf(W[2],  b.x, r);
                r = fmaf(W[3],  b.y, r);  r = fmaf(W[4],  b.z, r);
                r = fmaf(W[5],  b.w, r);  r = fmaf(W[6],  c.x, r);
                r = fmaf(W[7],  c.y, r);  r = fmaf(W[8],  c.z, r);
                r = fmaf(W[9],  c.w, r);  r = fmaf(W[10], d.x, r);
                r = fmaf(W[11], d.y, r);  r = fmaf(W[12], d.z, r);
                r = fmaf(W[13], d.w, r);  r = fmaf(W[14], e.x, r);
                r = fmaf(W[15], e.y, r);         // tap 15 = v[4oc+9]
            } else {
                r = 0.f;
#pragma unroll
                for (int k = 0; k < NTAP; ++k)
                    r = fmaf(W[k], srow[min(max(4 * oc - 6 + k, 0), IN_W - 1)], r);
            }
            outp[(size_t)j * OUT_W + oc] = r;
        }
        __syncthreads();                       // v4 safe for next strip
    }
}

extern "C" void kernel_launch(void* const* d_in, const int* in_sizes, int n_in,
                              void* d_out, int out_size)
{
    const float* in  = (const float*)d_in[0];
    float*       out = (float*)d_out;

    const int nimg = in_sizes[0] / (IN_H * IN_W);       // 24

    dim3 grid(XBLKS, nimg);                             // 32 x 24 = 768 blocks
    bicubic_fused<<<grid, 256>>>(in, out);
}